// round 1
// baseline (speedup 1.0000x reference)
#include <cuda_runtime.h>
#include <math.h>

#define N_PTS 32
#define D_DIM 128
#define ITERS 20
#define EPSF  1e-7f
#define CLIPF 1e-7f

__device__ double g_acc;

__global__ void zero_acc_kernel() { g_acc = 0.0; }

__global__ void finalize_kernel(float* out, float invG) {
    out[0] = (float)(g_acc * (double)invG);
}

__device__ __forceinline__ float warp_sum(float v) {
#pragma unroll
    for (int k = 16; k; k >>= 1) v += __shfl_xor_sync(0xffffffffu, v, k);
    return v;
}

// Compacting butterfly: reduces 32 independent per-lane arrays across the warp.
// On entry p[n] is this lane's partial for row n. On exit, return value is the
// full 32-lane sum for row == lane.
__device__ __forceinline__ float reduce32rows(float p[N_PTS], int lane) {
#pragma unroll
    for (int k = 16; k >= 1; k >>= 1) {
        bool up = (lane & k) != 0;
#pragma unroll
        for (int j = 0; j < k; j++) {
            float send = up ? p[j] : p[j + k];
            float keep = up ? p[j + k] : p[j];
            p[j] = keep + __shfl_xor_sync(0xffffffffu, send, k);
        }
    }
    return p[0];
}

__global__ __launch_bounds__(128) void karcher_kernel(const float* __restrict__ X) {
    const int g    = blockIdx.x;
    const int d    = threadIdx.x;     // this thread owns dimension d
    const int lane = d & 31;
    const int wid  = d >> 5;

    __shared__ float wsum[4][32];     // per-warp row partials
    __shared__ float c_sh[32];        // broadcast per-row coefficients
    __shared__ float bc0;             // broadcast scalar s = sum c[n]*dot[n]
    __shared__ float r4a[4], r4b[4];  // 4-warp scalar combine buffers

    const float* Xg = X + (size_t)g * (N_PTS * D_DIM);

    // ---- load: x[n] = X[g][n][d] (coalesced across threads) ----
    float x[N_PTS];
#pragma unroll
    for (int n = 0; n < N_PTS; n++) x[n] = __ldg(Xg + n * D_DIM + d);

    // ---- row-normalize all 32 points ----
    {
        float p[N_PTS];
#pragma unroll
        for (int n = 0; n < N_PTS; n++) p[n] = x[n] * x[n];
        float part = reduce32rows(p, lane);
        wsum[wid][lane] = part;
        __syncthreads();
        if (wid == 0) {
            float s = wsum[0][lane] + wsum[1][lane] + wsum[2][lane] + wsum[3][lane];
            c_sh[lane] = 1.0f / fmaxf(sqrtf(s), 1e-12f);
        }
        __syncthreads();
#pragma unroll
        for (int n = 0; n < N_PTS; n++) x[n] *= c_sh[n];
    }

    // ---- init mu = normalize(mean_n x[n]) ----
    float mu;
    {
        float m = 0.0f;
#pragma unroll
        for (int n = 0; n < N_PTS; n++) m += x[n];
        m *= (1.0f / N_PTS);
        float s2 = warp_sum(m * m);
        if (lane == 0) r4a[wid] = s2;
        __syncthreads();
        float n2 = r4a[0] + r4a[1] + r4a[2] + r4a[3];
        mu = m / fmaxf(sqrtf(n2), 1e-12f);
        __syncthreads();  // protect r4a before loop reuse
    }

    // ---- 20 fixed Karcher iterations (global done-flag dropped; see analysis) ----
    for (int it = 0; it < ITERS; it++) {
        // dots[n] = <mu, x[n]>  -- butterfly over the warp, combine 4 warps
        float p[N_PTS];
#pragma unroll
        for (int n = 0; n < N_PTS; n++) p[n] = x[n] * mu;
        float part = reduce32rows(p, lane);
        wsum[wid][lane] = part;
        __syncthreads();

        if (wid == 0) {
            float dot = wsum[0][lane] + wsum[1][lane] + wsum[2][lane] + wsum[3][lane];
            float t   = fminf(fmaxf(dot, -1.0f + CLIPF), 1.0f - CLIPF);
            float th  = acosf(t);
            float st  = fmaxf(sqrtf(fmaxf(1.0f - t * t, 0.0f)), EPSF);
            float c   = th / st;
            c_sh[lane] = c;
            float s = warp_sum(c * dot);   // sum_n c[n]*dot[n] (unclipped dot)
            if (lane == 0) bc0 = s;
        }
        __syncthreads();

        // v[d] = (1/N) * ( sum_n c[n]*x[n][d]  -  (sum_n c[n]*dot[n]) * mu[d] )
        float A = 0.0f;
#pragma unroll
        for (int n = 0; n < N_PTS; n++) A = fmaf(c_sh[n], x[n], A);
        float v = (A - bc0 * mu) * (1.0f / N_PTS);

        // ||v|| over all 128 dims
        float s2 = warp_sum(v * v);
        if (lane == 0) r4a[wid] = s2;
        __syncthreads();
        float vn2 = r4a[0] + r4a[1] + r4a[2] + r4a[3];
        float vn  = fmaxf(sqrtf(vn2), EPSF);

        // exp map + renormalize
        float mu_new = cosf(vn) * mu + (sinf(vn) / vn) * v;
        float m2 = warp_sum(mu_new * mu_new);
        if (lane == 0) r4b[wid] = m2;
        __syncthreads();
        float nn = r4b[0] + r4b[1] + r4b[2] + r4b[3];
        mu = mu_new / fmaxf(sqrtf(nn), 1e-12f);
        __syncthreads();  // protect r4a/r4b/wsum before next-iter reuse
    }

    // ---- loss_g = sum_n arccos(clip(<x[n], mu>))^2 ----
    {
        float p[N_PTS];
#pragma unroll
        for (int n = 0; n < N_PTS; n++) p[n] = x[n] * mu;
        float part = reduce32rows(p, lane);
        wsum[wid][lane] = part;
        __syncthreads();
        if (wid == 0) {
            float dot = wsum[0][lane] + wsum[1][lane] + wsum[2][lane] + wsum[3][lane];
            float t   = fminf(fmaxf(dot, -1.0f + CLIPF), 1.0f - CLIPF);
            float th  = acosf(t);
            float l   = warp_sum(th * th);
            if (lane == 0) atomicAdd(&g_acc, (double)l);
        }
    }
}

extern "C" void kernel_launch(void* const* d_in, const int* in_sizes, int n_in,
                              void* d_out, int out_size) {
    const float* X = (const float*)d_in[0];
    const int G = in_sizes[0] / (N_PTS * D_DIM);   // 8000 for (1000,8,32,128)

    zero_acc_kernel<<<1, 1>>>();
    karcher_kernel<<<G, 128>>>(X);
    finalize_kernel<<<1, 1>>>((float*)d_out, 1.0f / (float)G);
}

// round 2
// speedup vs baseline: 1.8834x; 1.8834x over previous
#include <cuda_runtime.h>
#include <math.h>

#define N_PTS 32
#define D_DIM 128
#define ITERS 20
#define EPSF  1e-7f
#define CLIPF 1e-7f
#define FULL  0xffffffffu

__device__ double g_acc;

__global__ void zero_acc_kernel() { g_acc = 0.0; }

__global__ void finalize_kernel(float* out, float invG) {
    out[0] = (float)(g_acc * (double)invG);
}

__device__ __forceinline__ float warp_sum(float v) {
#pragma unroll
    for (int k = 16; k; k >>= 1) v += __shfl_xor_sync(FULL, v, k);
    return v;
}

// Compacting butterfly: 32 independent 32-lane reductions in 31 shuffles.
// On entry p[n] = this lane's partial for row n; on exit the return value is
// the full sum for row == lane.
__device__ __forceinline__ float bfly32(float p[N_PTS], int lane) {
#pragma unroll
    for (int k = 16; k >= 1; k >>= 1) {
        bool up = (lane & k) != 0;
#pragma unroll
        for (int j = 0; j < k; j++) {
            float send = up ? p[j] : p[j + k];
            float keep = up ? p[j + k] : p[j];
            p[j] = keep + __shfl_xor_sync(FULL, send, k);
        }
    }
    return p[0];
}

__device__ __forceinline__ float dot4(const float4 a, const float4 b) {
    return fmaf(a.x, b.x, fmaf(a.y, b.y, fmaf(a.z, b.z, a.w * b.w)));
}

__global__ __launch_bounds__(32) void karcher_kernel(const float* __restrict__ X) {
    const int g    = blockIdx.x;
    const int lane = threadIdx.x;          // lane owns dims [4*lane, 4*lane+4)

    const float4* __restrict__ Xg =
        (const float4*)(X + (size_t)g * (N_PTS * D_DIM));

    // ---- load: x[n] = X[g][n][4*lane .. 4*lane+3], one LDG.128 per point ----
    float4 x[N_PTS];
#pragma unroll
    for (int n = 0; n < N_PTS; n++) x[n] = __ldg(&Xg[n * (D_DIM / 4) + lane]);

    // ---- row-normalize all 32 points (one butterfly) ----
    {
        float p[N_PTS];
#pragma unroll
        for (int n = 0; n < N_PTS; n++) p[n] = dot4(x[n], x[n]);
        float s  = bfly32(p, lane);                       // ||x[lane]||^2
        float rn = 1.0f / fmaxf(sqrtf(s), 1e-12f);
#pragma unroll
        for (int n = 0; n < N_PTS; n++) {
            float r = __shfl_sync(FULL, rn, n);
            x[n].x *= r; x[n].y *= r; x[n].z *= r; x[n].w *= r;
        }
    }

    // ---- init mu = normalize(mean_n x[n])  (mean is thread-local!) ----
    float4 mu;
    {
        float4 m = {0.f, 0.f, 0.f, 0.f};
#pragma unroll
        for (int n = 0; n < N_PTS; n++) {
            m.x += x[n].x; m.y += x[n].y; m.z += x[n].z; m.w += x[n].w;
        }
        const float invN = 1.0f / N_PTS;
        m.x *= invN; m.y *= invN; m.z *= invN; m.w *= invN;
        float n2 = warp_sum(dot4(m, m));
        float rn = 1.0f / fmaxf(sqrtf(n2), 1e-12f);
        mu.x = m.x * rn; mu.y = m.y * rn; mu.z = m.z * rn; mu.w = m.w * rn;
    }

    // ---- 20 fixed Karcher iterations, all intra-warp, no barriers ----
#pragma unroll 1
    for (int it = 0; it < ITERS; it++) {
        // dots[n] = <mu, x[n]>  — butterfly; lane ends with dot for point==lane
        float p[N_PTS];
#pragma unroll
        for (int n = 0; n < N_PTS; n++) p[n] = dot4(x[n], mu);
        float dot = bfly32(p, lane);

        // per-point scalar math, one point per lane
        float t  = fminf(fmaxf(dot, -1.0f + CLIPF), 1.0f - CLIPF);
        float th = acosf(t);
        float st = fmaxf(sqrtf(fmaxf(1.0f - t * t, 0.0f)), EPSF);
        float c  = th / st;

        // s = sum_n c[n]*dot[n]  (unclipped dot, matching reference diff term)
        float s = warp_sum(c * dot);

        // A[d] = sum_n c[n]*x[n][d]   (c broadcast lane->all via shfl)
        float4 A = {0.f, 0.f, 0.f, 0.f};
#pragma unroll
        for (int n = 0; n < N_PTS; n++) {
            float cn = __shfl_sync(FULL, c, n);
            A.x = fmaf(cn, x[n].x, A.x);
            A.y = fmaf(cn, x[n].y, A.y);
            A.z = fmaf(cn, x[n].z, A.z);
            A.w = fmaf(cn, x[n].w, A.w);
        }

        const float invN = 1.0f / N_PTS;
        float4 v;
        v.x = (A.x - s * mu.x) * invN;
        v.y = (A.y - s * mu.y) * invN;
        v.z = (A.z - s * mu.z) * invN;
        v.w = (A.w - s * mu.w) * invN;

        float vn2 = warp_sum(dot4(v, v));
        float vn  = fmaxf(sqrtf(vn2), EPSF);

        float sn, cs;
        sincosf(vn, &sn, &cs);
        float sc = sn / vn;

        float4 mn;
        mn.x = cs * mu.x + sc * v.x;
        mn.y = cs * mu.y + sc * v.y;
        mn.z = cs * mu.z + sc * v.z;
        mn.w = cs * mu.w + sc * v.w;

        float nn = warp_sum(dot4(mn, mn));
        float rn = 1.0f / fmaxf(sqrtf(nn), 1e-12f);
        mu.x = mn.x * rn; mu.y = mn.y * rn; mu.z = mn.z * rn; mu.w = mn.w * rn;
    }

    // ---- loss_g = sum_n arccos(clip(<x[n], mu>))^2 ----
    {
        float p[N_PTS];
#pragma unroll
        for (int n = 0; n < N_PTS; n++) p[n] = dot4(x[n], mu);
        float dot = bfly32(p, lane);
        float t  = fminf(fmaxf(dot, -1.0f + CLIPF), 1.0f - CLIPF);
        float th = acosf(t);
        float l  = warp_sum(th * th);
        if (lane == 0) atomicAdd(&g_acc, (double)l);
    }
}

extern "C" void kernel_launch(void* const* d_in, const int* in_sizes, int n_in,
                              void* d_out, int out_size) {
    const float* X = (const float*)d_in[0];
    const int G = in_sizes[0] / (N_PTS * D_DIM);   // 8000 for (1000,8,32,128)

    zero_acc_kernel<<<1, 1>>>();
    karcher_kernel<<<G, 32>>>(X);
    finalize_kernel<<<1, 1>>>((float*)d_out, 1.0f / (float)G);
}

// round 3
// speedup vs baseline: 2.4560x; 1.3040x over previous
#include <cuda_runtime.h>
#include <math.h>

#define N_PTS 32
#define D_DIM 128
#define ITERS 20
#define EPSF  1e-7f
#define CLIPF 1e-7f
#define FULL  0xffffffffu
#define RS    132     // smem row stride in floats (528B, 16B-aligned, bank-skewed)

__device__ double g_acc;

__global__ void zero_acc_kernel() { g_acc = 0.0; }

__global__ void finalize_kernel(float* out, float invG) {
    out[0] = (float)(g_acc * (double)invG);
}

__device__ __forceinline__ float warp_sum(float v) {
#pragma unroll
    for (int k = 16; k; k >>= 1) v += __shfl_xor_sync(FULL, v, k);
    return v;
}

// packed fp32x2 FMA (Blackwell): d += a*b elementwise on float2 packed in u64
__device__ __forceinline__ void ffma2(unsigned long long& d,
                                      unsigned long long a,
                                      unsigned long long b) {
    asm("fma.rn.f32x2 %0, %1, %2, %0;" : "+l"(d) : "l"(a), "l"(b));
}
__device__ __forceinline__ float hadd2(unsigned long long v) {
    float lo, hi;
    asm("mov.b64 {%0,%1}, %2;" : "=f"(lo), "=f"(hi) : "l"(v));
    return lo + hi;
}

__global__ __launch_bounds__(32) void karcher_kernel(const float* __restrict__ X) {
    __shared__ float Xs[N_PTS * RS];   // 16896 B; later reused for G (32x33)

    const int g    = blockIdx.x;
    const int lane = threadIdx.x;
    const float4* __restrict__ Xg = (const float4*)(X + (size_t)g * (N_PTS * D_DIM));

    // ================= Phase A: load group, swizzled store to smem ==========
    // Row r, logical 16B-tile t lives at physical tile (t + (r>>3)) & 31.
#pragma unroll
    for (int n = 0; n < N_PTS; n++) {
        float4 v = __ldg(&Xg[n * (D_DIM / 4) + lane]);
        int pt = (lane + (n >> 3)) & 31;
        *(float4*)&Xs[n * RS + 4 * pt] = v;
    }
    __syncwarp();

    // ================= Phase B: raw Gram G'[r][m], register-tiled ===========
    // lane (i,j): i = lane>>2 (8 row-blocks of 4), j = lane&3 (4 col-blocks of 8)
    const int i  = lane >> 2;
    const int j  = lane & 3;
    const int ih = i >> 1;             // (4i+rr)>>3 for rr in 0..3

    unsigned long long acc[4][8];
#pragma unroll
    for (int a = 0; a < 4; a++)
#pragma unroll
        for (int b = 0; b < 8; b++) acc[a][b] = 0ull;

    const float* pa = &Xs[(4 * i) * RS];
    const float* pb = &Xs[(8 * j) * RS];

#pragma unroll 4
    for (int t = 0; t < 32; t++) {
        int oa = ((t + ih) & 31) << 2;   // float offset of physical tile
        int ob = ((t + j)  & 31) << 2;

        ulonglong2 a0 = *(const ulonglong2*)(pa + 0 * RS + oa);
        ulonglong2 a1 = *(const ulonglong2*)(pa + 1 * RS + oa);
        ulonglong2 a2 = *(const ulonglong2*)(pa + 2 * RS + oa);
        ulonglong2 a3 = *(const ulonglong2*)(pa + 3 * RS + oa);

#pragma unroll
        for (int c = 0; c < 8; c++) {
            ulonglong2 b = *(const ulonglong2*)(pb + c * RS + ob);
            ffma2(acc[0][c], a0.x, b.x); ffma2(acc[0][c], a0.y, b.y);
            ffma2(acc[1][c], a1.x, b.x); ffma2(acc[1][c], a1.y, b.y);
            ffma2(acc[2][c], a2.x, b.x); ffma2(acc[2][c], a2.y, b.y);
            ffma2(acc[3][c], a3.x, b.x); ffma2(acc[3][c], a3.y, b.y);
        }
    }
    __syncwarp();                       // all Xs reads done before overwrite

    // scatter raw G to smem (reuse Xs), layout G[32][33]
    float* Gs = Xs;
#pragma unroll
    for (int rr = 0; rr < 4; rr++)
#pragma unroll
        for (int c = 0; c < 8; c++)
            Gs[33 * (4 * i + rr) + 8 * j + c] = hadd2(acc[rr][c]);
    __syncwarp();

    // ================= normalize G, init dots ===============================
    // lane = point n; gr[m] = <xn_n, xn_m> of row-normalized points
    float gr[N_PTS];
#pragma unroll
    for (int m = 0; m < N_PTS; m++) gr[m] = Gs[33 * lane + m];

    float dg = Gs[34 * lane];                       // diag = ||x_n||^2
    float rn = 1.0f / fmaxf(sqrtf(dg), 1e-12f);
#pragma unroll
    for (int m = 0; m < N_PTS; m++) {
        float rm = __shfl_sync(FULL, rn, m);
        gr[m] *= rn * rm;
    }

    // dots0[n] = <normalize(mean), x_n> = rowsum / max(sqrt(sum(G)),1e-12)
    float rowsum = 0.0f;
#pragma unroll
    for (int m = 0; m < N_PTS; m++) rowsum += gr[m];
    float T = warp_sum(rowsum);
    float dot = rowsum / fmaxf(sqrtf(T), 1e-12f);

    // ================= 20 Karcher iterations in dot space ===================
    const float invN = 1.0f / N_PTS;
#pragma unroll 1
    for (int it = 0; it < ITERS; it++) {
        float t  = fminf(fmaxf(dot, -1.0f + CLIPF), 1.0f - CLIPF);
        float th = acosf(t);
        float st = fmaxf(sqrtf(fmaf(-t, t, 1.0f)), EPSF);
        float c  = th / st;

        float s = warp_sum(c * dot);            // s = c . dots

        float gc0 = 0.f, gc1 = 0.f, gc2 = 0.f, gc3 = 0.f;
#pragma unroll
        for (int m = 0; m < N_PTS; m += 4) {
            float c0 = __shfl_sync(FULL, c, m);
            float c1 = __shfl_sync(FULL, c, m + 1);
            float c2 = __shfl_sync(FULL, c, m + 2);
            float c3 = __shfl_sync(FULL, c, m + 3);
            gc0 = fmaf(gr[m],     c0, gc0);
            gc1 = fmaf(gr[m + 1], c1, gc1);
            gc2 = fmaf(gr[m + 2], c2, gc2);
            gc3 = fmaf(gr[m + 3], c3, gc3);
        }
        float gc = (gc0 + gc1) + (gc2 + gc3);   // (G c)[n]

        float A2  = warp_sum(c * gc);           // |A|^2 = c^T G c
        float vn2 = fmaxf(A2 - s * s, 0.0f) * (invN * invN);
        float vn  = fmaxf(sqrtf(vn2), EPSF);

        float sn, cs;
        sincosf(vn, &sn, &cs);
        float sc = sn / vn;

        // dots <- cos*dots + (sin/|v|) * (Gc - s*dots)/N
        dot = fmaf(cs, dot, sc * invN * fmaf(-s, dot, gc));
    }

    // ================= loss =================================================
    {
        float t  = fminf(fmaxf(dot, -1.0f + CLIPF), 1.0f - CLIPF);
        float th = acosf(t);
        float l  = warp_sum(th * th);
        if (lane == 0) atomicAdd(&g_acc, (double)l);
    }
}

extern "C" void kernel_launch(void* const* d_in, const int* in_sizes, int n_in,
                              void* d_out, int out_size) {
    const float* X = (const float*)d_in[0];
    const int G = in_sizes[0] / (N_PTS * D_DIM);   // 8000 for (1000,8,32,128)

    zero_acc_kernel<<<1, 1>>>();
    karcher_kernel<<<G, 32>>>(X);
    finalize_kernel<<<1, 1>>>((float*)d_out, 1.0f / (float)G);
}

// round 6
// speedup vs baseline: 2.5522x; 1.0392x over previous
#include <cuda_runtime.h>
#include <math.h>

#define N_PTS 32
#define D_DIM 128
#define ITERS 20
#define EPSF  1e-7f
#define CLIPF 1e-7f
#define FULL  0xffffffffu
#define RS    132            // smem row stride in floats (528B)
#define MAXG  8192

__device__ double g_acc;
__device__ float  g_G[MAXG * 1024];   // per-group 32x32 Gram, [g][n][m]

__global__ void finalize_kernel(float* out, float invG) {
    out[0] = (float)(g_acc * (double)invG);
}

__device__ __forceinline__ float warp_sum(float v) {
#pragma unroll
    for (int k = 16; k; k >>= 1) v += __shfl_xor_sync(FULL, v, k);
    return v;
}

// packed fp32x2 FMA (Blackwell): d += a*b elementwise on float2 packed in u64
__device__ __forceinline__ void ffma2(unsigned long long& d,
                                      unsigned long long a,
                                      unsigned long long b) {
    asm("fma.rn.f32x2 %0, %1, %2, %0;" : "+l"(d) : "l"(a), "l"(b));
}
__device__ __forceinline__ float hadd2(unsigned long long v) {
    float lo, hi;
    asm("mov.b64 {%0,%1}, %2;" : "=f"(lo), "=f"(hi) : "l"(v));
    return lo + hi;
}

// ======================= Kernel 1: Gram (one warp/group) ====================
__global__ __launch_bounds__(32) void gram_kernel(const float* __restrict__ X) {
    __shared__ float Xs[N_PTS * RS];   // 16896 B staging; reused for G (32x33)

    const int g    = blockIdx.x;
    const int lane = threadIdx.x;

    if (g == 0 && lane == 0) g_acc = 0.0;   // stream-ordered before kernel 2

    const float4* __restrict__ Xg = (const float4*)(X + (size_t)g * (N_PTS * D_DIM));

    // ---- load group, swizzled store: row r, logical 16B-tile t at physical
    //      tile (t + (r>>3)) & 31 ----
#pragma unroll
    for (int n = 0; n < N_PTS; n++) {
        float4 v = __ldg(&Xg[n * (D_DIM / 4) + lane]);
        int pt = (lane + (n >> 3)) & 31;
        *(float4*)&Xs[n * RS + 4 * pt] = v;
    }
    __syncwarp();

    // ---- triangle tiles: 20 active lanes, tile (I,J), I>=2J ----
    // lane->tile map: J=0:I=0..7 | J=1:I=2..7 | J=2:I=4..7 | J=3:I=6..7
    int I, J;
    if      (lane < 8)  { J = 0; I = lane; }
    else if (lane < 14) { J = 1; I = lane - 6; }
    else if (lane < 18) { J = 2; I = lane - 10; }
    else                { J = 3; I = lane - 12; }
    const bool active = (lane < 20);

    unsigned long long acc[4][8];
#pragma unroll
    for (int a = 0; a < 4; a++)
#pragma unroll
        for (int b = 0; b < 8; b++) acc[a][b] = 0ull;

    if (active) {
        const int ih = I >> 1;
        const float* pa = &Xs[(4 * I) * RS];
        const float* pb = &Xs[(8 * J) * RS];
#pragma unroll 4
        for (int t = 0; t < 32; t++) {
            int oa = ((t + ih) & 31) << 2;
            int ob = ((t + J)  & 31) << 2;

            ulonglong2 a0 = *(const ulonglong2*)(pa + 0 * RS + oa);
            ulonglong2 a1 = *(const ulonglong2*)(pa + 1 * RS + oa);
            ulonglong2 a2 = *(const ulonglong2*)(pa + 2 * RS + oa);
            ulonglong2 a3 = *(const ulonglong2*)(pa + 3 * RS + oa);
#pragma unroll
            for (int c = 0; c < 8; c++) {
                ulonglong2 b = *(const ulonglong2*)(pb + c * RS + ob);
                ffma2(acc[0][c], a0.x, b.x); ffma2(acc[0][c], a0.y, b.y);
                ffma2(acc[1][c], a1.x, b.x); ffma2(acc[1][c], a1.y, b.y);
                ffma2(acc[2][c], a2.x, b.x); ffma2(acc[2][c], a2.y, b.y);
                ffma2(acc[3][c], a3.x, b.x); ffma2(acc[3][c], a3.y, b.y);
            }
        }
    }
    __syncwarp();                        // all Xs reads done before overwrite

    // ---- scatter G + mirror into smem (reuse Xs), layout G[32][33] ----
    float* Gs = Xs;
    if (active) {
#pragma unroll
        for (int rr = 0; rr < 4; rr++)
#pragma unroll
            for (int c = 0; c < 8; c++) {
                float v = hadd2(acc[rr][c]);
                int r = 4 * I + rr, cc = 8 * J + c;
                Gs[33 * r + cc] = v;
                Gs[33 * cc + r] = v;
            }
    }
    __syncwarp();

    // ---- coalesced copy-out: g_G[g][n][m] ----
    float* __restrict__ out = g_G + (size_t)g * 1024;
#pragma unroll
    for (int r = 0; r < N_PTS; r++)
        out[r * 32 + lane] = Gs[33 * r + lane];
}

// ================= Kernel 2: Karcher iterations in dot space ================
__global__ __launch_bounds__(256) void iter_kernel(int G) {
    const int warp = threadIdx.x >> 5;
    const int lane = threadIdx.x & 31;
    const int g    = blockIdx.x * 8 + warp;

    __shared__ float lsum[8];

    float l = 0.0f;
    if (g < G) {
        const float* __restrict__ Gp = g_G + (size_t)g * 1024;

        // gr[m] = G[m][lane] = G[lane][m] (symmetry -> coalesced)
        float gr[N_PTS];
#pragma unroll
        for (int m = 0; m < N_PTS; m++) gr[m] = __ldg(Gp + m * 32 + lane);

        float dg = __ldg(Gp + lane * 33);            // diag ||x_lane||^2
        float rn = 1.0f / fmaxf(sqrtf(dg), 1e-12f);
#pragma unroll
        for (int m = 0; m < N_PTS; m++) {
            float rm = __shfl_sync(FULL, rn, m);
            gr[m] *= rn * rm;
        }

        // dots0[n] = rowsum_n / max(sqrt(total), 1e-12)
        float rowsum = 0.0f;
#pragma unroll
        for (int m = 0; m < N_PTS; m++) rowsum += gr[m];
        float T = warp_sum(rowsum);
        float dot = rowsum / fmaxf(sqrtf(T), 1e-12f);

        const float invN = 1.0f / N_PTS;
#pragma unroll 1
        for (int it = 0; it < ITERS; it++) {
            float t  = fminf(fmaxf(dot, -1.0f + CLIPF), 1.0f - CLIPF);
            float th = acosf(t);
            float st = fmaxf(sqrtf(fmaf(-t, t, 1.0f)), EPSF);
            float c  = th / st;

            float s = warp_sum(c * dot);             // c . dots

            float gc0 = 0.f, gc1 = 0.f, gc2 = 0.f, gc3 = 0.f;
#pragma unroll
            for (int m = 0; m < N_PTS; m += 4) {
                float c0 = __shfl_sync(FULL, c, m);
                float c1 = __shfl_sync(FULL, c, m + 1);
                float c2 = __shfl_sync(FULL, c, m + 2);
                float c3 = __shfl_sync(FULL, c, m + 3);
                gc0 = fmaf(gr[m],     c0, gc0);
                gc1 = fmaf(gr[m + 1], c1, gc1);
                gc2 = fmaf(gr[m + 2], c2, gc2);
                gc3 = fmaf(gr[m + 3], c3, gc3);
            }
            float gc = (gc0 + gc1) + (gc2 + gc3);    // (G c)[lane]

            float A2  = warp_sum(c * gc);            // c^T G c
            float vn2 = fmaxf(A2 - s * s, 0.0f) * (invN * invN);
            float vn  = fmaxf(sqrtf(vn2), EPSF);

            float sn, cs;
            sincosf(vn, &sn, &cs);
            float sc = sn / vn;

            dot = fmaf(cs, dot, sc * invN * fmaf(-s, dot, gc));
        }

        float t  = fminf(fmaxf(dot, -1.0f + CLIPF), 1.0f - CLIPF);
        float th = acosf(t);
        l = warp_sum(th * th);
    }

    if (lane == 0) lsum[warp] = l;
    __syncthreads();
    if (threadIdx.x == 0) {
        float b = 0.0f;
#pragma unroll
        for (int w = 0; w < 8; w++) b += lsum[w];
        atomicAdd(&g_acc, (double)b);
    }
}

extern "C" void kernel_launch(void* const* d_in, const int* in_sizes, int n_in,
                              void* d_out, int out_size) {
    const float* X = (const float*)d_in[0];
    const int G = in_sizes[0] / (N_PTS * D_DIM);   // 8000 for (1000,8,32,128)

    gram_kernel<<<G, 32>>>(X);
    iter_kernel<<<(G + 7) / 8, 256>>>(G);
    finalize_kernel<<<1, 1>>>((float*)d_out, 1.0f / (float)G);
}